// round 2
// baseline (speedup 1.0000x reference)
#include <cuda_runtime.h>
#include <cstdint>

// ---------------------------------------------------------------------------
// SelfAttention: out = softmax(causal((x Wq)(x Wk)^T)/sqrt(d)) @ (x Wv)
// SEQ=4096, D=1024, all fp32.
// Round 1 baseline: pure-fp32 tiled SGEMMs (FMA pipe), causal block skip,
// fused row-normalization into the PV epilogue.
// ---------------------------------------------------------------------------

constexpr int SEQ = 4096;
constexpr int DIM = 1024;

// Scratch (static __device__ arrays: allowed; runtime allocs are not)
__device__ float g_Q[(size_t)SEQ * DIM];
__device__ float g_K[(size_t)SEQ * DIM];
__device__ float g_V[(size_t)SEQ * DIM];
__device__ float g_P[(size_t)SEQ * SEQ];   // logits, then unnormalized probs
__device__ float g_rinv[SEQ];              // 1 / softmax row sum

#define BM 128
#define BN 128
#define BK 16

// MODE 0: C = A(MxK) @ B(KxN)        (row-major NN)
// MODE 1: C = A(MxK) @ B(NxK)^T      (NT; skips blocks strictly above diagonal)
// KLIM:   limit K-loop to (bm+1)*BM (causal PV: P cols > row are zero)
// SCALE_ROWS: multiply output row m by rinv[m] in the epilogue
template <int MODE, bool KLIM, bool SCALE_ROWS>
__global__ __launch_bounds__(256)
void gemm128(const float* __restrict__ A, const float* __restrict__ B,
             float* __restrict__ C, int M, int N, int K,
             const float* __restrict__ rinv)
{
    const int bn = blockIdx.x, bm = blockIdx.y;
    if (MODE == 1 && bn > bm) return;   // causal: whole block above diagonal

    const int m0 = bm * BM, n0 = bn * BN;
    int Kend = K;
    if (KLIM) {
        int kl = (bm + 1) * BM;
        Kend = kl < K ? kl : K;
    }

    __shared__ float4 As4[BK][BM / 4];
    __shared__ float4 Bs4[BK][BN / 4];
    float* As = reinterpret_cast<float*>(As4);
    float* Bs = reinterpret_cast<float*>(Bs4);

    const int tid = threadIdx.x;
    const int tx = tid & 15;   // 16 col groups
    const int ty = tid >> 4;   // 16 row groups

    float acc[8][8];
#pragma unroll
    for (int i = 0; i < 8; i++)
#pragma unroll
        for (int j = 0; j < 8; j++) acc[i][j] = 0.0f;

    for (int k0 = 0; k0 < Kend; k0 += BK) {
        // --- A tile: BM x BK, stored transposed As[k][m] ---
#pragma unroll
        for (int it = 0; it < 2; it++) {
            int idx = tid + it * 256;          // 0..511 float4 slots
            int row = idx >> 2;                // 0..127
            int seg = idx & 3;                 // 4 float4 per row (BK=16)
            float4 v = *reinterpret_cast<const float4*>(
                &A[(size_t)(m0 + row) * K + k0 + seg * 4]);
            As[(seg * 4 + 0) * BM + row] = v.x;
            As[(seg * 4 + 1) * BM + row] = v.y;
            As[(seg * 4 + 2) * BM + row] = v.z;
            As[(seg * 4 + 3) * BM + row] = v.w;
        }
        // --- B tile ---
        if (MODE == 0) {
            // B is K x N: Bs[k][n], coalesced float4 rows
#pragma unroll
            for (int it = 0; it < 2; it++) {
                int idx = tid + it * 256;
                int r  = idx >> 5;             // 0..15
                int c4 = idx & 31;             // 0..31
                Bs4[r][c4] = *reinterpret_cast<const float4*>(
                    &B[(size_t)(k0 + r) * N + n0 + c4 * 4]);
            }
        } else {
            // B is N x K (row-major); need Bs[k][n] = B[n][k] -> transposed store
#pragma unroll
            for (int it = 0; it < 2; it++) {
                int idx = tid + it * 256;
                int row = idx >> 2;            // n index 0..127
                int seg = idx & 3;
                float4 v = *reinterpret_cast<const float4*>(
                    &B[(size_t)(n0 + row) * K + k0 + seg * 4]);
                Bs[(seg * 4 + 0) * BN + row] = v.x;
                Bs[(seg * 4 + 1) * BN + row] = v.y;
                Bs[(seg * 4 + 2) * BN + row] = v.z;
                Bs[(seg * 4 + 3) * BN + row] = v.w;
            }
        }
        __syncthreads();

#pragma unroll
        for (int kk = 0; kk < BK; kk++) {
            float4 a0 = As4[kk][ty];
            float4 a1 = As4[kk][ty + 16];
            float4 b0 = Bs4[kk][tx];
            float4 b1 = Bs4[kk][tx + 16];
            float ar[8] = {a0.x, a0.y, a0.z, a0.w, a1.x, a1.y, a1.z, a1.w};
            float br[8] = {b0.x, b0.y, b0.z, b0.w, b1.x, b1.y, b1.z, b1.w};
#pragma unroll
            for (int i = 0; i < 8; i++)
#pragma unroll
                for (int j = 0; j < 8; j++)
                    acc[i][j] += ar[i] * br[j];
        }
        __syncthreads();
    }

    // Epilogue: rows {ty*4..+3, 64+ty*4..+3}, cols {tx*4..+3, 64+tx*4..+3}
#pragma unroll
    for (int i = 0; i < 8; i++) {
        int m = (i < 4) ? (ty * 4 + i) : (64 + ty * 4 + (i - 4));
        float s = 1.0f;
        if (SCALE_ROWS) s = rinv[m0 + m];
        float4 v0 = make_float4(acc[i][0] * s, acc[i][1] * s,
                                acc[i][2] * s, acc[i][3] * s);
        float4 v1 = make_float4(acc[i][4] * s, acc[i][5] * s,
                                acc[i][6] * s, acc[i][7] * s);
        *reinterpret_cast<float4*>(&C[(size_t)(m0 + m) * N + n0 + tx * 4]) = v0;
        *reinterpret_cast<float4*>(&C[(size_t)(m0 + m) * N + n0 + 64 + tx * 4]) = v1;
    }
}

// Row-wise causal softmax on logits: p = exp((s - max)/sqrt(D)) for j<=row,
// 0 for row<j<klim (klim = next 128 boundary; PV never reads past it).
// Writes unnormalized p in place; 1/sum goes to rinv (applied in PV epilogue).
__global__ __launch_bounds__(256)
void softmax_causal(float* __restrict__ P, float* __restrict__ rinv)
{
    const int row   = blockIdx.x;
    const int valid = row + 1;
    const int klim  = ((row >> 7) + 1) << 7;
    float* prow = P + (size_t)row * SEQ;
    const int tid = threadIdx.x;
    __shared__ float red[256];

    // pass 1: max over valid logits
    float m = -3.402823466e38f;
    for (int j = tid; j < valid; j += 256) m = fmaxf(m, prow[j]);
    red[tid] = m;
    __syncthreads();
#pragma unroll
    for (int s = 128; s > 0; s >>= 1) {
        if (tid < s) red[tid] = fmaxf(red[tid], red[tid + s]);
        __syncthreads();
    }
    m = red[0];
    __syncthreads();

    // pass 2: exp + sum, zero the padding up to klim
    const float inv_sqrt_d = 0.03125f;   // 1/sqrt(1024)
    float sum = 0.0f;
    for (int j = tid; j < klim; j += 256) {
        float e = 0.0f;
        if (j < valid) e = __expf((prow[j] - m) * inv_sqrt_d);
        prow[j] = e;
        sum += e;
    }
    red[tid] = sum;
    __syncthreads();
#pragma unroll
    for (int s = 128; s > 0; s >>= 1) {
        if (tid < s) red[tid] += red[tid + s];
        __syncthreads();
    }
    if (tid == 0) rinv[row] = 1.0f / red[0];
}

extern "C" void kernel_launch(void* const* d_in, const int* in_sizes, int n_in,
                              void* d_out, int out_size)
{
    const float* x  = (const float*)d_in[0];
    const float* Wq = (const float*)d_in[1];
    const float* Wk = (const float*)d_in[2];
    const float* Wv = (const float*)d_in[3];
    float* out = (float*)d_out;

    float *Q, *K, *V, *P, *rinv;
    cudaGetSymbolAddress((void**)&Q,    g_Q);
    cudaGetSymbolAddress((void**)&K,    g_K);
    cudaGetSymbolAddress((void**)&V,    g_V);
    cudaGetSymbolAddress((void**)&P,    g_P);
    cudaGetSymbolAddress((void**)&rinv, g_rinv);

    dim3 blk(256);
    dim3 gridProj(DIM / BN, SEQ / BM);   // (8, 32)
    dim3 gridAttn(SEQ / BN, SEQ / BM);   // (32, 32)

    // Q, K, V projections
    gemm128<0, false, false><<<gridProj, blk>>>(x, Wq, Q, SEQ, DIM, DIM, nullptr);
    gemm128<0, false, false><<<gridProj, blk>>>(x, Wk, K, SEQ, DIM, DIM, nullptr);
    gemm128<0, false, false><<<gridProj, blk>>>(x, Wv, V, SEQ, DIM, DIM, nullptr);

    // Logits: P = Q @ K^T (lower-triangular blocks only)
    gemm128<1, false, false><<<gridAttn, blk>>>(Q, K, P, SEQ, SEQ, DIM, nullptr);

    // Causal softmax (unnormalized; row sums to rinv)
    softmax_causal<<<SEQ, 256>>>(P, rinv);

    // out = (P @ V) * rinv[row], K-loop limited to the causal extent
    gemm128<0, true, true><<<gridProj, blk>>>(P, V, out, SEQ, DIM, SEQ, rinv);
}

// round 7
// speedup vs baseline: 1.5800x; 1.5800x over previous
#include <cuda_runtime.h>
#include <cuda_bf16.h>
#include <cstdint>

// ---------------------------------------------------------------------------
// SelfAttention via mma.sync (HMMA) bf16-emulated-fp32 GEMMs.
// (tcgen05 is rejected by the harness's compute_103 virtual arch.)
// fp32 operand = sum of bf16 planes; 6 cross-products for QK path (~2^-26),
// 3 cross-products on 2-way splits for PV/V path (~2^-17).
// ---------------------------------------------------------------------------

constexpr int SEQ = 4096;
constexpr int DIM = 1024;

__device__ __nv_bfloat16 g_x3[3][(size_t)SEQ * DIM];
__device__ __nv_bfloat16 g_Wq3[3][(size_t)DIM * DIM];   // transposed [out][in]
__device__ __nv_bfloat16 g_Wk3[3][(size_t)DIM * DIM];
__device__ __nv_bfloat16 g_Wv3[2][(size_t)DIM * DIM];
__device__ __nv_bfloat16 g_Q3[3][(size_t)SEQ * DIM];
__device__ __nv_bfloat16 g_K3[3][(size_t)SEQ * DIM];
__device__ float         g_V[(size_t)SEQ * DIM];
__device__ __nv_bfloat16 g_Vt2[2][(size_t)DIM * SEQ];   // [dim][seq]
__device__ float         g_P[(size_t)SEQ * SEQ];        // logits
__device__ __nv_bfloat16 g_P2[2][(size_t)SEQ * SEQ];    // unnormalized probs
__device__ float         g_rinv[SEQ];

// ---------------- helpers ---------------------------------------------------
__device__ __forceinline__ uint32_t smem_u32(const void* p) {
    uint32_t a;
    asm("{ .reg .u64 t; cvta.to.shared.u64 t, %1; cvt.u32.u64 %0, t; }"
        : "=r"(a) : "l"(p));
    return a;
}
__device__ __forceinline__ void cp16(uint32_t s, const void* g) {
    asm volatile("cp.async.cg.shared.global [%0], [%1], 16;" :: "r"(s), "l"(g));
}
#define CP_COMMIT() asm volatile("cp.async.commit_group;" ::: "memory")
#define CP_WAIT1()  asm volatile("cp.async.wait_group 1;" ::: "memory")
#define CP_WAIT0()  asm volatile("cp.async.wait_group 0;" ::: "memory")

__device__ __forceinline__ void ldsm4(uint32_t* r, uint32_t addr) {
    asm volatile("ldmatrix.sync.aligned.m8n8.x4.shared.b16 {%0,%1,%2,%3}, [%4];"
                 : "=r"(r[0]), "=r"(r[1]), "=r"(r[2]), "=r"(r[3]) : "r"(addr));
}
__device__ __forceinline__ void mma16816(float* d, const uint32_t* a, const uint32_t* b) {
    asm volatile(
        "mma.sync.aligned.m16n8k16.row.col.f32.bf16.bf16.f32 "
        "{%0,%1,%2,%3}, {%4,%5,%6,%7}, {%8,%9}, {%0,%1,%2,%3};"
        : "+f"(d[0]), "+f"(d[1]), "+f"(d[2]), "+f"(d[3])
        : "r"(a[0]), "r"(a[1]), "r"(a[2]), "r"(a[3]), "r"(b[0]), "r"(b[1]));
}

__device__ __forceinline__ void split3(float v, __nv_bfloat16& a, __nv_bfloat16& b,
                                       __nv_bfloat16& c) {
    a = __float2bfloat16_rn(v);
    float r = v - __bfloat162float(a);
    b = __float2bfloat16_rn(r);
    c = __float2bfloat16_rn(r - __bfloat162float(b));
}
__device__ __forceinline__ void split2(float v, __nv_bfloat16& a, __nv_bfloat16& b) {
    a = __float2bfloat16_rn(v);
    b = __float2bfloat16_rn(v - __bfloat162float(a));
}

// ---------------- HMMA emulated-fp32 GEMM -----------------------------------
// C[128x128] = sum over plane pairs of Ap[pa] (M-K-major) @ Bp[pb]^T (N-K-major)
// EPI: 0 = f32 C, 1 = split3 -> 3 bf16 planes, 2 = f32 * rinv[row]
template <int PA, int PB, int NP, int EPI, bool CAUSAL, bool KLIMF>
__global__ __launch_bounds__(256, 1)
void hmma_gemm(const __nv_bfloat16* __restrict__ A0, const __nv_bfloat16* __restrict__ A1,
               const __nv_bfloat16* __restrict__ A2,
               const __nv_bfloat16* __restrict__ B0, const __nv_bfloat16* __restrict__ B1,
               const __nv_bfloat16* __restrict__ B2,
               int lda, int ldb, int K,
               float* __restrict__ Cf,
               __nv_bfloat16* __restrict__ O0, __nv_bfloat16* __restrict__ O1,
               __nv_bfloat16* __restrict__ O2,
               int ldc, const float* __restrict__ rinv)
{
    const int bn = blockIdx.x, bm = blockIdx.y;
    if (CAUSAL && bn > bm) return;
    const int m0 = bm * 128, n0 = bn * 128;

    constexpr int NPL = PA + PB;
    constexpr uint32_t RSTR = 80;                 // 32 bf16 = 64B rows, padded to 80B
    constexpr uint32_t PLSZ = 128 * RSTR;         // 10240
    constexpr uint32_t STAGE = NPL * PLSZ;

    extern __shared__ char smem_dyn[];
    const uint32_t sbase = (smem_u32(smem_dyn) + 1023u) & ~1023u;

    const int tid  = threadIdx.x;
    const int lane = tid & 31;
    const int wid  = tid >> 5;
    const int wm   = (wid >> 2) * 64;   // warp M offset in tile
    const int wn   = (wid & 3) * 32;    // warp N offset in tile

    const __nv_bfloat16* pl[NPL];
    pl[0] = A0; if (PA > 1) pl[1] = A1; if (PA > 2) pl[2] = A2;
    pl[PA] = B0; if (PB > 1) pl[PA + 1] = B1; if (PB > 2) pl[PA + 2] = B2;

    int Kend = K;
    if (KLIMF) { int kl = (bm + 1) * 128; Kend = kl < K ? kl : K; }
    const int nch = Kend >> 5;   // 32-k chunks

    auto load_stage = [&](int c, int buf) {
        const int k0 = c << 5;
        const uint32_t sb = sbase + buf * STAGE;
#pragma unroll
        for (int t = 0; t < NPL * 2; t++) {        // NPL*512 16B-chunks / 256 thr
            int idx = tid + t * 256;
            int plane = idx >> 9;
            int rem = idx & 511;
            int row = rem >> 2;
            int c4 = rem & 3;
            int rbase = (plane < PA) ? m0 : n0;
            int ld    = (plane < PA) ? lda : ldb;
            const __nv_bfloat16* g = pl[plane] + (size_t)(rbase + row) * ld + k0 + c4 * 8;
            cp16(sb + plane * PLSZ + row * RSTR + c4 * 16, g);
        }
        CP_COMMIT();
    };

    float acc[4][4][4];
#pragma unroll
    for (int i = 0; i < 4; i++)
#pragma unroll
        for (int j = 0; j < 4; j++)
#pragma unroll
            for (int q = 0; q < 4; q++) acc[i][j][q] = 0.0f;

    static constexpr int pa6[6] = {0, 0, 1, 0, 2, 1};
    static constexpr int pb6[6] = {0, 1, 0, 2, 0, 1};

    load_stage(0, 0);
    if (nch > 1) load_stage(1, 1);

    for (int c = 0; c < nch; c++) {
        if (c + 1 < nch) { CP_WAIT1(); } else { CP_WAIT0(); }
        __syncthreads();

        const uint32_t sb = sbase + (c & 1) * STAGE;
        // A frag lane addressing: row = wm + mt*16 + (lane&15), kbyte = (lane>=16)?16:0
        // B frag lane addressing: row = wn + nt2*16 + ((lane>>1)&8) + (lane&7),
        //                         kbyte = ((lane>>3)&1)*16
        const uint32_t a_row = (uint32_t)(wm + (lane & 15));
        const uint32_t a_kb  = ((uint32_t)(lane >> 4)) << 4;
        const uint32_t b_row = (uint32_t)(wn + ((lane >> 1) & 8) + (lane & 7));
        const uint32_t b_kb  = ((uint32_t)((lane >> 3) & 1)) << 4;

#pragma unroll
        for (int k16 = 0; k16 < 2; k16++) {
            uint32_t af[PA][4][4];
            uint32_t bfr[PB][8];
#pragma unroll
            for (int p = 0; p < PA; p++) {
                const uint32_t pbm = sb + p * PLSZ + k16 * 32 + a_kb;
#pragma unroll
                for (int mt = 0; mt < 4; mt++)
                    ldsm4(af[p][mt], pbm + (a_row + mt * 16) * RSTR);
            }
#pragma unroll
            for (int p = 0; p < PB; p++) {
                const uint32_t pbn = sb + (PA + p) * PLSZ + k16 * 32 + b_kb;
#pragma unroll
                for (int nt2 = 0; nt2 < 2; nt2++)
                    ldsm4(&bfr[p][nt2 * 4], pbn + (b_row + nt2 * 16) * RSTR);
            }
#pragma unroll
            for (int p = 0; p < NP; p++) {
                const int ia = pa6[p], ib = pb6[p];
#pragma unroll
                for (int mt = 0; mt < 4; mt++)
#pragma unroll
                    for (int nt = 0; nt < 4; nt++)
                        mma16816(acc[mt][nt], af[ia][mt], &bfr[ib][nt * 2]);
            }
        }
        __syncthreads();
        if (c + 2 < nch) load_stage(c + 2, c & 1);
    }

    // ---------------- epilogue (register accumulators) ----------------------
#pragma unroll
    for (int mt = 0; mt < 4; mt++) {
#pragma unroll
        for (int nt = 0; nt < 4; nt++) {
            const int gm = m0 + wm + mt * 16 + (lane >> 2);
            const int gn = n0 + wn + nt * 8 + (lane & 3) * 2;
            float c0 = acc[mt][nt][0], c1 = acc[mt][nt][1];
            float c2 = acc[mt][nt][2], c3 = acc[mt][nt][3];
            if (EPI == 0) {
                *reinterpret_cast<float2*>(&Cf[(size_t)gm * ldc + gn]) = make_float2(c0, c1);
                *reinterpret_cast<float2*>(&Cf[(size_t)(gm + 8) * ldc + gn]) = make_float2(c2, c3);
            } else if (EPI == 2) {
                float s0 = rinv[gm], s1 = rinv[gm + 8];
                *reinterpret_cast<float2*>(&Cf[(size_t)gm * ldc + gn]) =
                    make_float2(c0 * s0, c1 * s0);
                *reinterpret_cast<float2*>(&Cf[(size_t)(gm + 8) * ldc + gn]) =
                    make_float2(c2 * s1, c3 * s1);
            } else {
                __nv_bfloat16 a0, b0, d0, a1, b1, d1;
                split3(c0, a0, b0, d0); split3(c1, a1, b1, d1);
                __nv_bfloat162 t;
                t.x = a0; t.y = a1;
                *reinterpret_cast<__nv_bfloat162*>(&O0[(size_t)gm * ldc + gn]) = t;
                t.x = b0; t.y = b1;
                *reinterpret_cast<__nv_bfloat162*>(&O1[(size_t)gm * ldc + gn]) = t;
                t.x = d0; t.y = d1;
                *reinterpret_cast<__nv_bfloat162*>(&O2[(size_t)gm * ldc + gn]) = t;
                split3(c2, a0, b0, d0); split3(c3, a1, b1, d1);
                t.x = a0; t.y = a1;
                *reinterpret_cast<__nv_bfloat162*>(&O0[(size_t)(gm + 8) * ldc + gn]) = t;
                t.x = b0; t.y = b1;
                *reinterpret_cast<__nv_bfloat162*>(&O1[(size_t)(gm + 8) * ldc + gn]) = t;
                t.x = d0; t.y = d1;
                *reinterpret_cast<__nv_bfloat162*>(&O2[(size_t)(gm + 8) * ldc + gn]) = t;
            }
        }
    }
}

// ---------------- prep kernels ----------------------------------------------
__global__ void split3_kernel(const float* __restrict__ in, size_t n,
                              __nv_bfloat16* __restrict__ o0, __nv_bfloat16* __restrict__ o1,
                              __nv_bfloat16* __restrict__ o2)
{
    size_t i = (size_t)blockIdx.x * blockDim.x + threadIdx.x;
    size_t stride = (size_t)gridDim.x * blockDim.x;
    for (; i < n; i += stride) {
        __nv_bfloat16 a, b, c;
        split3(in[i], a, b, c);
        o0[i] = a; o1[i] = b; o2[i] = c;
    }
}

template <int NPL>
__global__ void tsplit_kernel(const float* __restrict__ in, int R, int C,
                              __nv_bfloat16* __restrict__ o0, __nv_bfloat16* __restrict__ o1,
                              __nv_bfloat16* __restrict__ o2)
{
    __shared__ float t[32][33];
    const int bc = blockIdx.x * 32, br = blockIdx.y * 32;
    const int tx = threadIdx.x, ty = threadIdx.y;   // 32 x 8
#pragma unroll
    for (int i = 0; i < 4; i++)
        t[ty + i * 8][tx] = in[(size_t)(br + ty + i * 8) * C + bc + tx];
    __syncthreads();
#pragma unroll
    for (int i = 0; i < 4; i++) {
        float v = t[tx][ty + i * 8];
        size_t o = (size_t)(bc + ty + i * 8) * R + br + tx;
        if (NPL == 3) {
            __nv_bfloat16 a, b, c;
            split3(v, a, b, c);
            o0[o] = a; o1[o] = b; o2[o] = c;
        } else {
            __nv_bfloat16 a, b;
            split2(v, a, b);
            o0[o] = a; o1[o] = b;
        }
    }
}

__global__ __launch_bounds__(256)
void softmax_split(const float* __restrict__ P, __nv_bfloat16* __restrict__ P0,
                   __nv_bfloat16* __restrict__ P1, float* __restrict__ rinv)
{
    const int row   = blockIdx.x;
    const int valid = row + 1;
    const int klim  = ((row >> 7) + 1) << 7;
    const float* prow = P + (size_t)row * SEQ;
    const int tid = threadIdx.x;
    __shared__ float red[256];

    float m = -3.402823466e38f;
    for (int j = tid; j < valid; j += 256) m = fmaxf(m, prow[j]);
    red[tid] = m;
    __syncthreads();
#pragma unroll
    for (int s = 128; s > 0; s >>= 1) {
        if (tid < s) red[tid] = fmaxf(red[tid], red[tid + s]);
        __syncthreads();
    }
    m = red[0];
    __syncthreads();

    const float inv_sqrt_d = 0.03125f;
    float sum = 0.0f;
    for (int j = tid; j < klim; j += 256) {
        float e = 0.0f;
        if (j < valid) e = __expf((prow[j] - m) * inv_sqrt_d);
        __nv_bfloat16 a, b;
        split2(e, a, b);
        P0[(size_t)row * SEQ + j] = a;
        P1[(size_t)row * SEQ + j] = b;
        sum += e;
    }
    red[tid] = sum;
    __syncthreads();
#pragma unroll
    for (int s = 128; s > 0; s >>= 1) {
        if (tid < s) red[tid] += red[tid + s];
        __syncthreads();
    }
    if (tid == 0) rinv[row] = 1.0f / red[0];
}

// ---------------- host side --------------------------------------------------
extern "C" void kernel_launch(void* const* d_in, const int* in_sizes, int n_in,
                              void* d_out, int out_size)
{
    const float* x  = (const float*)d_in[0];
    const float* Wq = (const float*)d_in[1];
    const float* Wk = (const float*)d_in[2];
    const float* Wv = (const float*)d_in[3];
    float* out = (float*)d_out;

    __nv_bfloat16 *x3[3], *Wq3[3], *Wk3[3], *Wv3[2], *Q3[3], *K3[3], *Vt2[2], *P2[2];
    float *V, *P, *rinv;
    for (int i = 0; i < 3; i++) {
        cudaGetSymbolAddress((void**)&x3[i],  g_x3);  x3[i]  += (size_t)i * SEQ * DIM;
        cudaGetSymbolAddress((void**)&Wq3[i], g_Wq3); Wq3[i] += (size_t)i * DIM * DIM;
        cudaGetSymbolAddress((void**)&Wk3[i], g_Wk3); Wk3[i] += (size_t)i * DIM * DIM;
        cudaGetSymbolAddress((void**)&Q3[i],  g_Q3);  Q3[i]  += (size_t)i * SEQ * DIM;
        cudaGetSymbolAddress((void**)&K3[i],  g_K3);  K3[i]  += (size_t)i * SEQ * DIM;
    }
    for (int i = 0; i < 2; i++) {
        cudaGetSymbolAddress((void**)&Wv3[i], g_Wv3); Wv3[i] += (size_t)i * DIM * DIM;
        cudaGetSymbolAddress((void**)&Vt2[i], g_Vt2); Vt2[i] += (size_t)i * DIM * SEQ;
        cudaGetSymbolAddress((void**)&P2[i],  g_P2);  P2[i]  += (size_t)i * SEQ * SEQ;
    }
    cudaGetSymbolAddress((void**)&V,    g_V);
    cudaGetSymbolAddress((void**)&P,    g_P);
    cudaGetSymbolAddress((void**)&rinv, g_rinv);

    auto gemm_split  = hmma_gemm<3, 3, 6, 1, false, false>;  // Q/K proj -> bf16 planes
    auto gemm_vproj  = hmma_gemm<2, 2, 3, 0, false, false>;  // V proj -> f32
    auto gemm_causal = hmma_gemm<3, 3, 6, 0, true,  false>;  // QK^T -> f32 logits
    auto gemm_pv     = hmma_gemm<2, 2, 3, 2, false, true>;   // PV -> out

    const int SM6 = 2 * 6 * 10240 + 1024;   // 123904
    const int SM4 = 2 * 4 * 10240 + 1024;   // 82944
    cudaFuncSetAttribute(gemm_split,  cudaFuncAttributeMaxDynamicSharedMemorySize, SM6);
    cudaFuncSetAttribute(gemm_vproj,  cudaFuncAttributeMaxDynamicSharedMemorySize, SM4);
    cudaFuncSetAttribute(gemm_causal, cudaFuncAttributeMaxDynamicSharedMemorySize, SM6);
    cudaFuncSetAttribute(gemm_pv,     cudaFuncAttributeMaxDynamicSharedMemorySize, SM4);

    // 1) operand splits
    split3_kernel<<<1024, 256>>>(x, (size_t)SEQ * DIM, x3[0], x3[1], x3[2]);
    dim3 tb(32, 8);
    tsplit_kernel<3><<<dim3(DIM / 32, DIM / 32), tb>>>(Wq, DIM, DIM, Wq3[0], Wq3[1], Wq3[2]);
    tsplit_kernel<3><<<dim3(DIM / 32, DIM / 32), tb>>>(Wk, DIM, DIM, Wk3[0], Wk3[1], Wk3[2]);
    tsplit_kernel<2><<<dim3(DIM / 32, DIM / 32), tb>>>(Wv, DIM, DIM, Wv3[0], Wv3[1], nullptr);

    dim3 gProj(DIM / 128, SEQ / 128);     // (8, 32)
    dim3 gAttn(SEQ / 128, SEQ / 128);     // (32, 32)

    // 2) projections
    gemm_split<<<gProj, 256, SM6>>>(x3[0], x3[1], x3[2], Wq3[0], Wq3[1], Wq3[2],
                                    DIM, DIM, DIM, nullptr, Q3[0], Q3[1], Q3[2], DIM, nullptr);
    gemm_split<<<gProj, 256, SM6>>>(x3[0], x3[1], x3[2], Wk3[0], Wk3[1], Wk3[2],
                                    DIM, DIM, DIM, nullptr, K3[0], K3[1], K3[2], DIM, nullptr);
    gemm_vproj<<<gProj, 256, SM4>>>(x3[0], x3[1], nullptr, Wv3[0], Wv3[1], nullptr,
                                    DIM, DIM, DIM, V, nullptr, nullptr, nullptr, DIM, nullptr);

    // 3) V -> Vt (split2, transposed)
    tsplit_kernel<2><<<dim3(DIM / 32, SEQ / 32), tb>>>(V, SEQ, DIM, Vt2[0], Vt2[1], nullptr);

    // 4) logits (lower-triangular blocks only)
    gemm_causal<<<gAttn, 256, SM6>>>(Q3[0], Q3[1], Q3[2], K3[0], K3[1], K3[2],
                                     DIM, DIM, DIM, P, nullptr, nullptr, nullptr, SEQ, nullptr);

    // 5) softmax + split of unnormalized probs
    softmax_split<<<SEQ, 256>>>(P, P2[0], P2[1], rinv);

    // 6) out = (P @ V) * rinv, causal K-limit
    gemm_pv<<<gProj, 256, SM4>>>(P2[0], P2[1], nullptr, Vt2[0], Vt2[1], nullptr,
                                 SEQ, SEQ, SEQ, out, nullptr, nullptr, nullptr, DIM, rinv);
}

// round 8
// speedup vs baseline: 2.3230x; 1.4702x over previous
#include <cuda_runtime.h>
#include <cuda_fp16.h>
#include <cstdint>

// ---------------------------------------------------------------------------
// SelfAttention via mma.sync (HMMA) fp16-emulated-fp32 GEMMs.
// fp32 operand = hi + lo (fp16 planes, exact residual split, 11+11 bits).
// 3 pair-products (hh, hl, lh) -> ~2^-22 relative error on every GEMM.
// ---------------------------------------------------------------------------

constexpr int SEQ = 4096;
constexpr int DIM = 1024;

__device__ __half g_x2[2][(size_t)SEQ * DIM];
__device__ __half g_Wq2[2][(size_t)DIM * DIM];   // transposed [out][in]
__device__ __half g_Wk2[2][(size_t)DIM * DIM];
__device__ __half g_Wv2[2][(size_t)DIM * DIM];
__device__ __half g_Q2[2][(size_t)SEQ * DIM];
__device__ __half g_K2[2][(size_t)SEQ * DIM];
__device__ float  g_V[(size_t)SEQ * DIM];
__device__ __half g_Vt2[2][(size_t)DIM * SEQ];   // [dim][seq]
__device__ float  g_P[(size_t)SEQ * SEQ];        // logits
__device__ __half g_P2[2][(size_t)SEQ * SEQ];    // unnormalized probs
__device__ float  g_rinv[SEQ];

// ---------------- helpers ---------------------------------------------------
__device__ __forceinline__ uint32_t smem_u32(const void* p) {
    uint32_t a;
    asm("{ .reg .u64 t; cvta.to.shared.u64 t, %1; cvt.u32.u64 %0, t; }"
        : "=r"(a) : "l"(p));
    return a;
}
__device__ __forceinline__ void cp16(uint32_t s, const void* g) {
    asm volatile("cp.async.cg.shared.global [%0], [%1], 16;" :: "r"(s), "l"(g));
}
#define CP_COMMIT() asm volatile("cp.async.commit_group;" ::: "memory")
#define CP_WAIT1()  asm volatile("cp.async.wait_group 1;" ::: "memory")
#define CP_WAIT0()  asm volatile("cp.async.wait_group 0;" ::: "memory")

__device__ __forceinline__ void ldsm4(uint32_t* r, uint32_t addr) {
    asm volatile("ldmatrix.sync.aligned.m8n8.x4.shared.b16 {%0,%1,%2,%3}, [%4];"
                 : "=r"(r[0]), "=r"(r[1]), "=r"(r[2]), "=r"(r[3]) : "r"(addr));
}
__device__ __forceinline__ void mma16816(float* d, const uint32_t* a, const uint32_t* b) {
    asm volatile(
        "mma.sync.aligned.m16n8k16.row.col.f32.f16.f16.f32 "
        "{%0,%1,%2,%3}, {%4,%5,%6,%7}, {%8,%9}, {%0,%1,%2,%3};"
        : "+f"(d[0]), "+f"(d[1]), "+f"(d[2]), "+f"(d[3])
        : "r"(a[0]), "r"(a[1]), "r"(a[2]), "r"(a[3]), "r"(b[0]), "r"(b[1]));
}

__device__ __forceinline__ void split2h(float v, __half& a, __half& b) {
    a = __float2half_rn(v);
    b = __float2half_rn(v - __half2float(a));
}

// ---------------- HMMA emulated-fp32 GEMM -----------------------------------
// C[128x128] = sum of 3 plane pairs: Ap (M-K-major fp16) @ Bp^T (N-K-major fp16)
// EPI: 0 = f32 C, 1 = split2 -> 2 fp16 planes, 2 = f32 * rinv[row]
template <int EPI, bool CAUSAL, bool KLIMF>
__global__ __launch_bounds__(256, 2)
void hmma_gemm(const __half* __restrict__ A0, const __half* __restrict__ A1,
               const __half* __restrict__ B0, const __half* __restrict__ B1,
               int lda, int ldb, int K,
               float* __restrict__ Cf,
               __half* __restrict__ O0, __half* __restrict__ O1,
               int ldc, const float* __restrict__ rinv)
{
    const int bn = blockIdx.x, bm = blockIdx.y;
    if (CAUSAL && bn > bm) return;
    const int m0 = bm * 128, n0 = bn * 128;

    constexpr int NPL = 4;                        // Ahi, Alo, Bhi, Blo
    constexpr uint32_t RSTR = 80;                 // 32 fp16 = 64B rows, padded to 80B
    constexpr uint32_t PLSZ = 128 * RSTR;         // 10240
    constexpr uint32_t STAGE = NPL * PLSZ;        // 40960

    extern __shared__ char smem_dyn[];
    const uint32_t sbase = (smem_u32(smem_dyn) + 1023u) & ~1023u;

    const int tid  = threadIdx.x;
    const int lane = tid & 31;
    const int wid  = tid >> 5;
    const int wm   = (wid >> 2) * 64;   // warp M offset
    const int wn   = (wid & 3) * 32;    // warp N offset

    const __half* pl[NPL] = {A0, A1, B0, B1};

    int Kend = K;
    if (KLIMF) { int kl = (bm + 1) * 128; Kend = kl < K ? kl : K; }
    const int nch = Kend >> 5;   // 32-k chunks

    auto load_stage = [&](int c, int buf) {
        const int k0 = c << 5;
        const uint32_t sb = sbase + buf * STAGE;
#pragma unroll
        for (int t = 0; t < NPL * 2; t++) {        // NPL*512 16B-chunks / 256 thr
            int idx = tid + t * 256;
            int plane = idx >> 9;
            int rem = idx & 511;
            int row = rem >> 2;
            int c4 = rem & 3;
            int rbase = (plane < 2) ? m0 : n0;
            int ld    = (plane < 2) ? lda : ldb;
            const __half* g = pl[plane] + (size_t)(rbase + row) * ld + k0 + c4 * 8;
            cp16(sb + plane * PLSZ + row * RSTR + c4 * 16, g);
        }
        CP_COMMIT();
    };

    float acc[4][4][4];
#pragma unroll
    for (int i = 0; i < 4; i++)
#pragma unroll
        for (int j = 0; j < 4; j++)
#pragma unroll
            for (int q = 0; q < 4; q++) acc[i][j][q] = 0.0f;

    static constexpr int pa3[3] = {0, 0, 1};
    static constexpr int pb3[3] = {0, 1, 0};

    load_stage(0, 0);
    if (nch > 1) load_stage(1, 1);

    for (int c = 0; c < nch; c++) {
        if (c + 1 < nch) { CP_WAIT1(); } else { CP_WAIT0(); }
        __syncthreads();

        const uint32_t sb = sbase + (c & 1) * STAGE;
        const uint32_t a_row = (uint32_t)(wm + (lane & 15));
        const uint32_t a_kb  = ((uint32_t)(lane >> 4)) << 4;
        const uint32_t b_row = (uint32_t)(wn + ((lane >> 1) & 8) + (lane & 7));
        const uint32_t b_kb  = ((uint32_t)((lane >> 3) & 1)) << 4;

#pragma unroll
        for (int k16 = 0; k16 < 2; k16++) {
            uint32_t af[2][4][4];
            uint32_t bfr[2][8];
#pragma unroll
            for (int p = 0; p < 2; p++) {
                const uint32_t pbm = sb + p * PLSZ + k16 * 32 + a_kb;
#pragma unroll
                for (int mt = 0; mt < 4; mt++)
                    ldsm4(af[p][mt], pbm + (a_row + mt * 16) * RSTR);
            }
#pragma unroll
            for (int p = 0; p < 2; p++) {
                const uint32_t pbn = sb + (2 + p) * PLSZ + k16 * 32 + b_kb;
#pragma unroll
                for (int nt2 = 0; nt2 < 2; nt2++)
                    ldsm4(&bfr[p][nt2 * 4], pbn + (b_row + nt2 * 16) * RSTR);
            }
#pragma unroll
            for (int p = 0; p < 3; p++) {
                const int ia = pa3[p], ib = pb3[p];
#pragma unroll
                for (int mt = 0; mt < 4; mt++)
#pragma unroll
                    for (int nt = 0; nt < 4; nt++)
                        mma16816(acc[mt][nt], af[ia][mt], &bfr[ib][nt * 2]);
            }
        }
        __syncthreads();
        if (c + 2 < nch) load_stage(c + 2, c & 1);
    }

    // ---------------- epilogue ----------------------------------------------
#pragma unroll
    for (int mt = 0; mt < 4; mt++) {
#pragma unroll
        for (int nt = 0; nt < 4; nt++) {
            const int gm = m0 + wm + mt * 16 + (lane >> 2);
            const int gn = n0 + wn + nt * 8 + (lane & 3) * 2;
            float c0 = acc[mt][nt][0], c1 = acc[mt][nt][1];
            float c2 = acc[mt][nt][2], c3 = acc[mt][nt][3];
            if (EPI == 0) {
                *reinterpret_cast<float2*>(&Cf[(size_t)gm * ldc + gn]) = make_float2(c0, c1);
                *reinterpret_cast<float2*>(&Cf[(size_t)(gm + 8) * ldc + gn]) = make_float2(c2, c3);
            } else if (EPI == 2) {
                float s0 = rinv[gm], s1 = rinv[gm + 8];
                *reinterpret_cast<float2*>(&Cf[(size_t)gm * ldc + gn]) =
                    make_float2(c0 * s0, c1 * s0);
                *reinterpret_cast<float2*>(&Cf[(size_t)(gm + 8) * ldc + gn]) =
                    make_float2(c2 * s1, c3 * s1);
            } else {
                __half a0, b0, a1, b1;
                __half2 t;
                split2h(c0, a0, b0); split2h(c1, a1, b1);
                t.x = a0; t.y = a1;
                *reinterpret_cast<__half2*>(&O0[(size_t)gm * ldc + gn]) = t;
                t.x = b0; t.y = b1;
                *reinterpret_cast<__half2*>(&O1[(size_t)gm * ldc + gn]) = t;
                split2h(c2, a0, b0); split2h(c3, a1, b1);
                t.x = a0; t.y = a1;
                *reinterpret_cast<__half2*>(&O0[(size_t)(gm + 8) * ldc + gn]) = t;
                t.x = b0; t.y = b1;
                *reinterpret_cast<__half2*>(&O1[(size_t)(gm + 8) * ldc + gn]) = t;
            }
        }
    }
}

// ---------------- prep kernels ----------------------------------------------
__global__ void split2_kernel(const float* __restrict__ in, size_t n,
                              __half* __restrict__ o0, __half* __restrict__ o1)
{
    size_t i = (size_t)blockIdx.x * blockDim.x + threadIdx.x;
    size_t stride = (size_t)gridDim.x * blockDim.x;
    for (; i < n; i += stride) {
        __half a, b;
        split2h(in[i], a, b);
        o0[i] = a; o1[i] = b;
    }
}

// transpose + split2: in [R, C] f32 -> planes [C, R] fp16
__global__ void tsplit2_kernel(const float* __restrict__ in, int R, int C,
                               __half* __restrict__ o0, __half* __restrict__ o1)
{
    __shared__ float t[32][33];
    const int bc = blockIdx.x * 32, br = blockIdx.y * 32;
    const int tx = threadIdx.x, ty = threadIdx.y;   // 32 x 8
#pragma unroll
    for (int i = 0; i < 4; i++)
        t[ty + i * 8][tx] = in[(size_t)(br + ty + i * 8) * C + bc + tx];
    __syncthreads();
#pragma unroll
    for (int i = 0; i < 4; i++) {
        float v = t[tx][ty + i * 8];
        size_t o = (size_t)(bc + ty + i * 8) * R + br + tx;
        __half a, b;
        split2h(v, a, b);
        o0[o] = a; o1[o] = b;
    }
}

__global__ __launch_bounds__(256)
void softmax_split(const float* __restrict__ P, __half* __restrict__ P0,
                   __half* __restrict__ P1, float* __restrict__ rinv)
{
    const int row   = blockIdx.x;
    const int valid = row + 1;
    const int klim  = ((row >> 7) + 1) << 7;
    const float* prow = P + (size_t)row * SEQ;
    const int tid = threadIdx.x;
    __shared__ float red[256];

    float m = -3.402823466e38f;
    for (int j = tid; j < valid; j += 256) m = fmaxf(m, prow[j]);
    red[tid] = m;
    __syncthreads();
#pragma unroll
    for (int s = 128; s > 0; s >>= 1) {
        if (tid < s) red[tid] = fmaxf(red[tid], red[tid + s]);
        __syncthreads();
    }
    m = red[0];
    __syncthreads();

    const float inv_sqrt_d = 0.03125f;
    float sum = 0.0f;
    for (int j = tid; j < klim; j += 256) {
        float e = 0.0f;
        if (j < valid) e = __expf((prow[j] - m) * inv_sqrt_d);
        __half a, b;
        split2h(e, a, b);
        P0[(size_t)row * SEQ + j] = a;
        P1[(size_t)row * SEQ + j] = b;
        sum += e;
    }
    red[tid] = sum;
    __syncthreads();
#pragma unroll
    for (int s = 128; s > 0; s >>= 1) {
        if (tid < s) red[tid] += red[tid + s];
        __syncthreads();
    }
    if (tid == 0) rinv[row] = 1.0f / red[0];
}

// ---------------- host side --------------------------------------------------
extern "C" void kernel_launch(void* const* d_in, const int* in_sizes, int n_in,
                              void* d_out, int out_size)
{
    const float* x  = (const float*)d_in[0];
    const float* Wq = (const float*)d_in[1];
    const float* Wk = (const float*)d_in[2];
    const float* Wv = (const float*)d_in[3];
    float* out = (float*)d_out;

    __half *x2[2], *Wq2[2], *Wk2[2], *Wv2[2], *Q2[2], *K2[2], *Vt2[2], *P2[2];
    float *V, *P, *rinv;
    for (int i = 0; i < 2; i++) {
        cudaGetSymbolAddress((void**)&x2[i],  g_x2);  x2[i]  += (size_t)i * SEQ * DIM;
        cudaGetSymbolAddress((void**)&Wq2[i], g_Wq2); Wq2[i] += (size_t)i * DIM * DIM;
        cudaGetSymbolAddress((void**)&Wk2[i], g_Wk2); Wk2[i] += (size_t)i * DIM * DIM;
        cudaGetSymbolAddress((void**)&Wv2[i], g_Wv2); Wv2[i] += (size_t)i * DIM * DIM;
        cudaGetSymbolAddress((void**)&Q2[i],  g_Q2);  Q2[i]  += (size_t)i * SEQ * DIM;
        cudaGetSymbolAddress((void**)&K2[i],  g_K2);  K2[i]  += (size_t)i * SEQ * DIM;
        cudaGetSymbolAddress((void**)&Vt2[i], g_Vt2); Vt2[i] += (size_t)i * DIM * SEQ;
        cudaGetSymbolAddress((void**)&P2[i],  g_P2);  P2[i]  += (size_t)i * SEQ * SEQ;
    }
    cudaGetSymbolAddress((void**)&V,    g_V);
    cudaGetSymbolAddress((void**)&P,    g_P);
    cudaGetSymbolAddress((void**)&rinv, g_rinv);

    auto gemm_proj   = hmma_gemm<1, false, false>;  // Q/K proj -> fp16 planes
    auto gemm_vproj  = hmma_gemm<0, false, false>;  // V proj -> f32
    auto gemm_causal = hmma_gemm<0, true,  false>;  // QK^T -> f32 logits
    auto gemm_pv     = hmma_gemm<2, false, true>;   // PV -> out

    const int SM = 2 * 4 * 10240 + 1024;   // 82944
    cudaFuncSetAttribute(gemm_proj,   cudaFuncAttributeMaxDynamicSharedMemorySize, SM);
    cudaFuncSetAttribute(gemm_vproj,  cudaFuncAttributeMaxDynamicSharedMemorySize, SM);
    cudaFuncSetAttribute(gemm_causal, cudaFuncAttributeMaxDynamicSharedMemorySize, SM);
    cudaFuncSetAttribute(gemm_pv,     cudaFuncAttributeMaxDynamicSharedMemorySize, SM);

    // 1) operand splits
    split2_kernel<<<1024, 256>>>(x, (size_t)SEQ * DIM, x2[0], x2[1]);
    dim3 tb(32, 8);
    tsplit2_kernel<<<dim3(DIM / 32, DIM / 32), tb>>>(Wq, DIM, DIM, Wq2[0], Wq2[1]);
    tsplit2_kernel<<<dim3(DIM / 32, DIM / 32), tb>>>(Wk, DIM, DIM, Wk2[0], Wk2[1]);
    tsplit2_kernel<<<dim3(DIM / 32, DIM / 32), tb>>>(Wv, DIM, DIM, Wv2[0], Wv2[1]);

    dim3 gProj(DIM / 128, SEQ / 128);     // (8, 32)
    dim3 gAttn(SEQ / 128, SEQ / 128);     // (32, 32)

    // 2) projections
    gemm_proj<<<gProj, 256, SM>>>(x2[0], x2[1], Wq2[0], Wq2[1],
                                  DIM, DIM, DIM, nullptr, Q2[0], Q2[1], DIM, nullptr);
    gemm_proj<<<gProj, 256, SM>>>(x2[0], x2[1], Wk2[0], Wk2[1],
                                  DIM, DIM, DIM, nullptr, K2[0], K2[1], DIM, nullptr);
    gemm_vproj<<<gProj, 256, SM>>>(x2[0], x2[1], Wv2[0], Wv2[1],
                                   DIM, DIM, DIM, V, nullptr, nullptr, DIM, nullptr);

    // 3) V -> Vt (split2, transposed)
    tsplit2_kernel<<<dim3(DIM / 32, SEQ / 32), tb>>>(V, SEQ, DIM, Vt2[0], Vt2[1]);

    // 4) logits (lower-triangular blocks only)
    gemm_causal<<<gAttn, 256, SM>>>(Q2[0], Q2[1], K2[0], K2[1],
                                    DIM, DIM, DIM, P, nullptr, nullptr, SEQ, nullptr);

    // 5) softmax + split2 of unnormalized probs
    softmax_split<<<SEQ, 256>>>(P, P2[0], P2[1], rinv);

    // 6) out = (P @ V) * rinv, causal K-limit
    gemm_pv<<<gProj, 256, SM>>>(P2[0], P2[1], Vt2[0], Vt2[1],
                                SEQ, SEQ, SEQ, out, nullptr, nullptr, DIM, rinv);
}

// round 9
// speedup vs baseline: 2.6365x; 1.1350x over previous
#include <cuda_runtime.h>
#include <cuda_fp16.h>
#include <cstdint>

// ---------------------------------------------------------------------------
// SelfAttention via mma.sync (HMMA) fp16-emulated-fp32 GEMMs.
// fp32 operand = hi + lo fp16 planes; 3 pair-products (hh,hl,lh) ~2^-22.
// PV path: P rounded to fp16 (hi only), normalized by the rounded sum ->
// 2 pair-products; error ~1e-4.
// ---------------------------------------------------------------------------

constexpr int SEQ = 4096;
constexpr int DIM = 1024;

__device__ __half g_x2[2][(size_t)SEQ * DIM];
__device__ __half g_Wq2[2][(size_t)DIM * DIM];   // transposed [out][in]
__device__ __half g_Wk2[2][(size_t)DIM * DIM];
__device__ __half g_Wv2[2][(size_t)DIM * DIM];
__device__ __half g_Q2[2][(size_t)SEQ * DIM];
__device__ __half g_K2[2][(size_t)SEQ * DIM];
__device__ float  g_V[(size_t)SEQ * DIM];
__device__ __half g_Vt2[2][(size_t)DIM * SEQ];   // [dim][seq]
__device__ float  g_P[(size_t)SEQ * SEQ];        // logits
__device__ __half g_Ph[(size_t)SEQ * SEQ];       // fp16 unnormalized probs
__device__ float  g_rinv[SEQ];

// ---------------- helpers ---------------------------------------------------
__device__ __forceinline__ uint32_t smem_u32(const void* p) {
    uint32_t a;
    asm("{ .reg .u64 t; cvta.to.shared.u64 t, %1; cvt.u32.u64 %0, t; }"
        : "=r"(a) : "l"(p));
    return a;
}
__device__ __forceinline__ void cp16(uint32_t s, const void* g) {
    asm volatile("cp.async.cg.shared.global [%0], [%1], 16;" :: "r"(s), "l"(g));
}
#define CP_COMMIT() asm volatile("cp.async.commit_group;" ::: "memory")
#define CP_WAIT1()  asm volatile("cp.async.wait_group 1;" ::: "memory")
#define CP_WAIT0()  asm volatile("cp.async.wait_group 0;" ::: "memory")

__device__ __forceinline__ void ldsm4(uint32_t* r, uint32_t addr) {
    asm volatile("ldmatrix.sync.aligned.m8n8.x4.shared.b16 {%0,%1,%2,%3}, [%4];"
                 : "=r"(r[0]), "=r"(r[1]), "=r"(r[2]), "=r"(r[3]) : "r"(addr));
}
__device__ __forceinline__ void mma16816(float* d, const uint32_t* a, const uint32_t* b) {
    asm volatile(
        "mma.sync.aligned.m16n8k16.row.col.f32.f16.f16.f32 "
        "{%0,%1,%2,%3}, {%4,%5,%6,%7}, {%8,%9}, {%0,%1,%2,%3};"
        : "+f"(d[0]), "+f"(d[1]), "+f"(d[2]), "+f"(d[3])
        : "r"(a[0]), "r"(a[1]), "r"(a[2]), "r"(a[3]), "r"(b[0]), "r"(b[1]));
}

__device__ __forceinline__ void split2h(float v, __half& a, __half& b) {
    a = __float2half_rn(v);
    b = __float2half_rn(v - __half2float(a));
}

// ---------------- HMMA emulated-fp32 GEMM -----------------------------------
// C[128x128] = sum over NPAIR plane pairs Ap[paA[p]] @ Bp[paB[p]]^T
// A planes M-K-major fp16, B planes N-K-major fp16.
// EPI: 0 = f32 C, 1 = split2 -> 2 fp16 planes, 2 = f32 * rinv[row]
// COMPACT: 1D lower-triangular grid (QK^T causal)
template <int NA, int NB, int NPAIR, int EPI, bool KLIMF, bool COMPACT>
__global__ __launch_bounds__(256, 2)
void hmma_gemm(const __half* __restrict__ A0, const __half* __restrict__ A1,
               const __half* __restrict__ B0, const __half* __restrict__ B1,
               int lda, int ldb, int K,
               float* __restrict__ Cf,
               __half* __restrict__ O0, __half* __restrict__ O1,
               int ldc, const float* __restrict__ rinv)
{
    int bn, bm;
    if (COMPACT) {
        int t = blockIdx.x;
        bm = (int)((sqrtf(8.0f * t + 1.0f) - 1.0f) * 0.5f);
        while ((bm + 1) * (bm + 2) / 2 <= t) bm++;
        while (bm * (bm + 1) / 2 > t) bm--;
        bn = t - bm * (bm + 1) / 2;
    } else {
        bn = blockIdx.x; bm = blockIdx.y;
    }
    const int m0 = bm * 128, n0 = bn * 128;

    constexpr int NPL = NA + NB;
    constexpr uint32_t RSTR = 80;                 // 32 fp16 rows padded to 80B
    constexpr uint32_t PLSZ = 128 * RSTR;         // 10240
    constexpr uint32_t STAGE = NPL * PLSZ;

    extern __shared__ char smem_dyn[];
    const uint32_t sbase = (smem_u32(smem_dyn) + 1023u) & ~1023u;

    const int tid  = threadIdx.x;
    const int lane = tid & 31;
    const int wid  = tid >> 5;
    const int wm   = (wid >> 2) * 64;   // warp M offset
    const int wn   = (wid & 3) * 32;    // warp N offset

    const __half* pl[NPL];
    pl[0] = A0; if (NA > 1) pl[1] = A1;
    pl[NA] = B0; if (NB > 1) pl[NA + 1] = B1;

    int Kend = K;
    if (KLIMF) { int kl = (bm + 1) * 128; Kend = kl < K ? kl : K; }
    const int nch = Kend >> 5;   // 32-k chunks

    auto load_stage = [&](int c, int buf) {
        const int k0 = c << 5;
        const uint32_t sb = sbase + buf * STAGE;
#pragma unroll
        for (int t = 0; t < NPL * 2; t++) {
            int idx = tid + t * 256;
            int plane = idx >> 9;
            int rem = idx & 511;
            int row = rem >> 2;
            int c4 = rem & 3;
            int rbase = (plane < NA) ? m0 : n0;
            int ld    = (plane < NA) ? lda : ldb;
            const __half* g = pl[plane] + (size_t)(rbase + row) * ld + k0 + c4 * 8;
            cp16(sb + plane * PLSZ + row * RSTR + c4 * 16, g);
        }
        CP_COMMIT();
    };

    float acc[4][4][4];
#pragma unroll
    for (int i = 0; i < 4; i++)
#pragma unroll
        for (int j = 0; j < 4; j++)
#pragma unroll
            for (int q = 0; q < 4; q++) acc[i][j][q] = 0.0f;

    // pair tables: 3-pair = (0,0),(0,1),(1,0); 2-pair = (0,0),(0,1)
    constexpr int paA[3] = {0, 0, 1};
    constexpr int paB[3] = {0, 1, 0};

    load_stage(0, 0);
    if (nch > 1) load_stage(1, 1);

    for (int c = 0; c < nch; c++) {
        if (c + 1 < nch) { CP_WAIT1(); } else { CP_WAIT0(); }
        __syncthreads();

        const uint32_t sb = sbase + (c & 1) * STAGE;
        const uint32_t a_row = (uint32_t)(wm + (lane & 15));
        const uint32_t a_kb  = ((uint32_t)(lane >> 4)) << 4;
        const uint32_t b_row = (uint32_t)(wn + ((lane >> 1) & 8) + (lane & 7));
        const uint32_t b_kb  = ((uint32_t)((lane >> 3) & 1)) << 4;

#pragma unroll
        for (int k16 = 0; k16 < 2; k16++) {
            // all B-plane fragments (NB*8 regs)
            uint32_t bfr[NB][8];
#pragma unroll
            for (int p = 0; p < NB; p++) {
                const uint32_t pbn = sb + (NA + p) * PLSZ + k16 * 32 + b_kb;
#pragma unroll
                for (int nt2 = 0; nt2 < 2; nt2++)
                    ldsm4(&bfr[p][nt2 * 4], pbn + (b_row + nt2 * 16) * RSTR);
            }
            // A planes one at a time (16 regs reused) to bound live registers
#pragma unroll
            for (int ia = 0; ia < NA; ia++) {
                uint32_t af[4][4];
                const uint32_t pbm = sb + ia * PLSZ + k16 * 32 + a_kb;
#pragma unroll
                for (int mt = 0; mt < 4; mt++)
                    ldsm4(af[mt], pbm + (a_row + mt * 16) * RSTR);
#pragma unroll
                for (int p = 0; p < NPAIR; p++) {
                    if (paA[p] != ia) continue;
                    const int ib = paB[p];
#pragma unroll
                    for (int mt = 0; mt < 4; mt++)
#pragma unroll
                        for (int nt = 0; nt < 4; nt++)
                            mma16816(acc[mt][nt], af[mt], &bfr[ib][nt * 2]);
                }
            }
        }
        __syncthreads();
        if (c + 2 < nch) load_stage(c + 2, c & 1);
    }

    // ---------------- epilogue ----------------------------------------------
#pragma unroll
    for (int mt = 0; mt < 4; mt++) {
#pragma unroll
        for (int nt = 0; nt < 4; nt++) {
            const int gm = m0 + wm + mt * 16 + (lane >> 2);
            const int gn = n0 + wn + nt * 8 + (lane & 3) * 2;
            float c0 = acc[mt][nt][0], c1 = acc[mt][nt][1];
            float c2 = acc[mt][nt][2], c3 = acc[mt][nt][3];
            if (EPI == 0) {
                *reinterpret_cast<float2*>(&Cf[(size_t)gm * ldc + gn]) = make_float2(c0, c1);
                *reinterpret_cast<float2*>(&Cf[(size_t)(gm + 8) * ldc + gn]) = make_float2(c2, c3);
            } else if (EPI == 2) {
                float s0 = rinv[gm], s1 = rinv[gm + 8];
                *reinterpret_cast<float2*>(&Cf[(size_t)gm * ldc + gn]) =
                    make_float2(c0 * s0, c1 * s0);
                *reinterpret_cast<float2*>(&Cf[(size_t)(gm + 8) * ldc + gn]) =
                    make_float2(c2 * s1, c3 * s1);
            } else {
                __half a0, b0, a1, b1;
                __half2 t;
                split2h(c0, a0, b0); split2h(c1, a1, b1);
                t.x = a0; t.y = a1;
                *reinterpret_cast<__half2*>(&O0[(size_t)gm * ldc + gn]) = t;
                t.x = b0; t.y = b1;
                *reinterpret_cast<__half2*>(&O1[(size_t)gm * ldc + gn]) = t;
                split2h(c2, a0, b0); split2h(c3, a1, b1);
                t.x = a0; t.y = a1;
                *reinterpret_cast<__half2*>(&O0[(size_t)(gm + 8) * ldc + gn]) = t;
                t.x = b0; t.y = b1;
                *reinterpret_cast<__half2*>(&O1[(size_t)(gm + 8) * ldc + gn]) = t;
            }
        }
    }
}

// ---------------- prep kernels ----------------------------------------------
__global__ void split2_kernel(const float* __restrict__ in, size_t n,
                              __half* __restrict__ o0, __half* __restrict__ o1)
{
    size_t i = (size_t)blockIdx.x * blockDim.x + threadIdx.x;
    size_t stride = (size_t)gridDim.x * blockDim.x;
    for (; i < n; i += stride) {
        __half a, b;
        split2h(in[i], a, b);
        o0[i] = a; o1[i] = b;
    }
}

// transpose + split2: in [R, C] f32 -> planes [C, R] fp16
__global__ void tsplit2_kernel(const float* __restrict__ in, int R, int C,
                               __half* __restrict__ o0, __half* __restrict__ o1)
{
    __shared__ float t[32][33];
    const int bc = blockIdx.x * 32, br = blockIdx.y * 32;
    const int tx = threadIdx.x, ty = threadIdx.y;   // 32 x 8
#pragma unroll
    for (int i = 0; i < 4; i++)
        t[ty + i * 8][tx] = in[(size_t)(br + ty + i * 8) * C + bc + tx];
    __syncthreads();
#pragma unroll
    for (int i = 0; i < 4; i++) {
        float v = t[tx][ty + i * 8];
        size_t o = (size_t)(bc + ty + i * 8) * R + br + tx;
        __half a, b;
        split2h(v, a, b);
        o0[o] = a; o1[o] = b;
    }
}

// causal softmax: exp -> fp16 (hi only); rinv = 1 / sum(rounded values) so the
// PV normalization cancels the systematic rounding of P.
__global__ __launch_bounds__(256)
void softmax_h(const float* __restrict__ P, __half* __restrict__ Ph,
               float* __restrict__ rinv)
{
    const int row   = blockIdx.x;
    const int valid = row + 1;
    const int klim  = ((row >> 7) + 1) << 7;
    const float* prow = P + (size_t)row * SEQ;
    const int tid = threadIdx.x;
    __shared__ float red[256];

    float m = -3.402823466e38f;
    for (int j = tid; j < valid; j += 256) m = fmaxf(m, prow[j]);
    red[tid] = m;
    __syncthreads();
#pragma unroll
    for (int s = 128; s > 0; s >>= 1) {
        if (tid < s) red[tid] = fmaxf(red[tid], red[tid + s]);
        __syncthreads();
    }
    m = red[0];
    __syncthreads();

    const float inv_sqrt_d = 0.03125f;
    float sum = 0.0f;
    for (int j = tid; j < klim; j += 256) {
        float e = 0.0f;
        if (j < valid) e = __expf((prow[j] - m) * inv_sqrt_d);
        __half h = __float2half_rn(e);
        Ph[(size_t)row * SEQ + j] = h;
        sum += __half2float(h);
    }
    red[tid] = sum;
    __syncthreads();
#pragma unroll
    for (int s = 128; s > 0; s >>= 1) {
        if (tid < s) red[tid] += red[tid + s];
        __syncthreads();
    }
    if (tid == 0) rinv[row] = 1.0f / red[0];
}

// ---------------- host side --------------------------------------------------
extern "C" void kernel_launch(void* const* d_in, const int* in_sizes, int n_in,
                              void* d_out, int out_size)
{
    const float* x  = (const float*)d_in[0];
    const float* Wq = (const float*)d_in[1];
    const float* Wk = (const float*)d_in[2];
    const float* Wv = (const float*)d_in[3];
    float* out = (float*)d_out;

    __half *x2[2], *Wq2[2], *Wk2[2], *Wv2[2], *Q2[2], *K2[2], *Vt2[2];
    __half *Ph;
    float *V, *P, *rinv;
    for (int i = 0; i < 2; i++) {
        cudaGetSymbolAddress((void**)&x2[i],  g_x2);  x2[i]  += (size_t)i * SEQ * DIM;
        cudaGetSymbolAddress((void**)&Wq2[i], g_Wq2); Wq2[i] += (size_t)i * DIM * DIM;
        cudaGetSymbolAddress((void**)&Wk2[i], g_Wk2); Wk2[i] += (size_t)i * DIM * DIM;
        cudaGetSymbolAddress((void**)&Wv2[i], g_Wv2); Wv2[i] += (size_t)i * DIM * DIM;
        cudaGetSymbolAddress((void**)&Q2[i],  g_Q2);  Q2[i]  += (size_t)i * SEQ * DIM;
        cudaGetSymbolAddress((void**)&K2[i],  g_K2);  K2[i]  += (size_t)i * SEQ * DIM;
        cudaGetSymbolAddress((void**)&Vt2[i], g_Vt2); Vt2[i] += (size_t)i * DIM * SEQ;
    }
    cudaGetSymbolAddress((void**)&Ph,   g_Ph);
    cudaGetSymbolAddress((void**)&V,    g_V);
    cudaGetSymbolAddress((void**)&P,    g_P);
    cudaGetSymbolAddress((void**)&rinv, g_rinv);

    auto gemm_proj   = hmma_gemm<2, 2, 3, 1, false, false>;  // Q/K proj -> fp16 planes
    auto gemm_vproj  = hmma_gemm<2, 2, 3, 0, false, false>;  // V proj -> f32
    auto gemm_causal = hmma_gemm<2, 2, 3, 0, false, true>;   // QK^T -> f32 logits (compact)
    auto gemm_pv     = hmma_gemm<1, 2, 2, 2, true,  false>;  // PV -> out (K-limit)

    const int SM4 = 2 * 4 * 10240 + 1024;   // 82944
    const int SM3 = 2 * 3 * 10240 + 1024;   // 62464
    cudaFuncSetAttribute(gemm_proj,   cudaFuncAttributeMaxDynamicSharedMemorySize, SM4);
    cudaFuncSetAttribute(gemm_vproj,  cudaFuncAttributeMaxDynamicSharedMemorySize, SM4);
    cudaFuncSetAttribute(gemm_causal, cudaFuncAttributeMaxDynamicSharedMemorySize, SM4);
    cudaFuncSetAttribute(gemm_pv,     cudaFuncAttributeMaxDynamicSharedMemorySize, SM3);

    // 1) operand splits
    split2_kernel<<<1024, 256>>>(x, (size_t)SEQ * DIM, x2[0], x2[1]);
    dim3 tb(32, 8);
    tsplit2_kernel<<<dim3(DIM / 32, DIM / 32), tb>>>(Wq, DIM, DIM, Wq2[0], Wq2[1]);
    tsplit2_kernel<<<dim3(DIM / 32, DIM / 32), tb>>>(Wk, DIM, DIM, Wk2[0], Wk2[1]);
    tsplit2_kernel<<<dim3(DIM / 32, DIM / 32), tb>>>(Wv, DIM, DIM, Wv2[0], Wv2[1]);

    dim3 gProj(DIM / 128, SEQ / 128);     // (8, 32)

    // 2) projections
    gemm_proj<<<gProj, 256, SM4>>>(x2[0], x2[1], Wq2[0], Wq2[1],
                                   DIM, DIM, DIM, nullptr, Q2[0], Q2[1], DIM, nullptr);
    gemm_proj<<<gProj, 256, SM4>>>(x2[0], x2[1], Wk2[0], Wk2[1],
                                   DIM, DIM, DIM, nullptr, K2[0], K2[1], DIM, nullptr);
    gemm_vproj<<<gProj, 256, SM4>>>(x2[0], x2[1], Wv2[0], Wv2[1],
                                    DIM, DIM, DIM, V, nullptr, nullptr, DIM, nullptr);

    // 3) V -> Vt (split2, transposed)
    tsplit2_kernel<<<dim3(DIM / 32, SEQ / 32), tb>>>(V, SEQ, DIM, Vt2[0], Vt2[1]);

    // 4) logits: compact lower-triangular grid (528 CTAs)
    gemm_causal<<<dim3(32 * 33 / 2), 256, SM4>>>(Q2[0], Q2[1], K2[0], K2[1],
                                                 DIM, DIM, DIM, P, nullptr, nullptr, SEQ, nullptr);

    // 5) softmax -> fp16 probs + rinv of rounded sum
    softmax_h<<<SEQ, 256>>>(P, Ph, rinv);

    // 6) out = (Ph @ V) * rinv, causal K-limit; A = single plane Ph
    gemm_pv<<<gProj, 256, SM3>>>(Ph, nullptr, Vt2[0], Vt2[1],
                                 SEQ, SEQ, SEQ, out, nullptr, nullptr, DIM, rinv);
}